// round 4
// baseline (speedup 1.0000x reference)
#include <cuda_runtime.h>
#include <cstddef>

// Causal GQA prefill attention, fp32 I/O. B=2,S=2048,H=32,KVH=8,D=128.
// Flash attention on tensor cores: mma.sync.m16n8k8 tf32, fp32 accumulate.
// 128 threads = 4 warps; warp w owns q-rows [w*16, w*16+16) of a 64-row tile.

#define NTH 128

__device__ __forceinline__ unsigned tf32(float f) {
    unsigned u; asm("cvt.rna.tf32.f32 %0, %1;" : "=r"(u) : "f"(f));
    return u;
}
__device__ __forceinline__ void mma8(float* c, const unsigned* a, unsigned b0, unsigned b1) {
    asm("mma.sync.aligned.m16n8k8.row.col.f32.tf32.tf32.f32 "
        "{%0,%1,%2,%3}, {%4,%5,%6,%7}, {%8,%9}, {%0,%1,%2,%3};"
        : "+f"(c[0]), "+f"(c[1]), "+f"(c[2]), "+f"(c[3])
        : "r"(a[0]), "r"(a[1]), "r"(a[2]), "r"(a[3]), "r"(b0), "r"(b1));
}

// smem (uint words): K 64x136 @0, V 64x136 @8704, P 64x68 @17408 ; total 21760 w
#define SM_K 0
#define SM_V 8704
#define SM_P 17408
#define SM_WORDS 21760

__global__ void __launch_bounds__(NTH, 2)
fa_tc_kernel(const float* __restrict__ q, const float* __restrict__ k,
             const float* __restrict__ v, float* __restrict__ out)
{
    extern __shared__ unsigned sm[];
    unsigned* Ks = sm + SM_K;
    unsigned* Vs = sm + SM_V;
    unsigned* Ps = sm + SM_P;

    const int qt   = (int)gridDim.x - 1 - (int)blockIdx.x;  // heavy tiles first
    const int h    = blockIdx.y;
    const int b    = blockIdx.z;
    const int kvh  = h >> 2;
    const int tid  = threadIdx.x;
    const int w    = tid >> 5;          // warp: rows w*16..w*16+15
    const int lane = tid & 31;
    const int g    = lane >> 2;         // groupID 0..7
    const int t    = lane & 3;          // threadID_in_group 0..3
    const float scale = 0.08838834764831845f;  // 1/sqrt(128)

    // ---- Q fragments in registers (scale folded in, cvt.rna to tf32) ----
    unsigned qf[16][4];
    {
        const float* qb = q + (((size_t)b * 2048 + (size_t)qt * 64 + w * 16) * 32 + h) * 128;
        const float* r0 = qb + (size_t)g * 4096;
        const float* r1 = qb + (size_t)(g + 8) * 4096;
        #pragma unroll
        for (int ks = 0; ks < 16; ++ks) {
            qf[ks][0] = tf32(r0[ks * 8 + t] * scale);
            qf[ks][1] = tf32(r1[ks * 8 + t] * scale);
            qf[ks][2] = tf32(r0[ks * 8 + t + 4] * scale);
            qf[ks][3] = tf32(r1[ks * 8 + t + 4] * scale);
        }
    }

    float O[16][4];
    #pragma unroll
    for (int nt = 0; nt < 16; ++nt)
        #pragma unroll
        for (int r = 0; r < 4; ++r) O[nt][r] = 0.0f;
    float m0 = -1e30f, m1 = -1e30f, l0 = 0.0f, l1 = 0.0f;

    const float* kb0 = k + ((size_t)b * 8 + kvh) * 2048 * 128;
    const float* vb0 = v + ((size_t)b * 8 + kvh) * 2048 * 128;
    const int row0 = qt * 64 + w * 16 + g;   // global q rows this thread owns
    const int row1 = row0 + 8;

    for (int kt = 0; kt <= qt; ++kt) {
        __syncthreads();
        // ---- load K,V tiles (64x128) -> smem stride 136, cvt to tf32 ----
        {
            const float* kb = kb0 + (size_t)kt * 8192;
            const float* vb = vb0 + (size_t)kt * 8192;
            #pragma unroll
            for (int it = 0; it < 16; ++it) {
                int idx = it * NTH + tid, row = idx >> 5, c = idx & 31;
                int d4 = (row * 34 + c) * 4;
                float4 a = *(const float4*)(kb + idx * 4);
                Ks[d4] = tf32(a.x); Ks[d4 + 1] = tf32(a.y);
                Ks[d4 + 2] = tf32(a.z); Ks[d4 + 3] = tf32(a.w);
                float4 e = *(const float4*)(vb + idx * 4);
                Vs[d4] = tf32(e.x); Vs[d4 + 1] = tf32(e.y);
                Vs[d4 + 2] = tf32(e.z); Vs[d4 + 3] = tf32(e.w);
            }
        }
        __syncthreads();

        const bool diag = (kt == qt);
        const int nt_max = diag ? 2 * w + 2 : 8;   // S column tiles (n=8 each)
        const int ks_max = diag ? 2 * w + 2 : 8;   // PV k tiles

        // ---- S = (Q*scale) K^T ----
        float S[8][4];
        #pragma unroll
        for (int nt = 0; nt < 8; ++nt)
            #pragma unroll
            for (int r = 0; r < 4; ++r) S[nt][r] = 0.0f;

        #pragma unroll
        for (int ks = 0; ks < 16; ++ks)
            #pragma unroll 8
            for (int nt = 0; nt < 8; ++nt) {
                if (nt >= nt_max) break;
                const unsigned* kr = Ks + (nt * 8 + g) * 136 + ks * 8 + t;
                mma8(S[nt], qf[ks], kr[0], kr[4]);
            }

        // ---- causal mask on diagonal tile ----
        if (diag) {
            #pragma unroll
            for (int nt = 0; nt < 8; ++nt) {
                int c0 = kt * 64 + nt * 8 + 2 * t;
                if (c0 > row0)     S[nt][0] = -1e30f;
                if (c0 + 1 > row0) S[nt][1] = -1e30f;
                if (c0 > row1)     S[nt][2] = -1e30f;
                if (c0 + 1 > row1) S[nt][3] = -1e30f;
            }
        }

        // ---- online softmax (rows row0/row1 live in quad lanes) ----
        float mx0 = -1e30f, mx1 = -1e30f;
        #pragma unroll
        for (int nt = 0; nt < 8; ++nt) {
            if (nt >= nt_max) break;
            mx0 = fmaxf(mx0, fmaxf(S[nt][0], S[nt][1]));
            mx1 = fmaxf(mx1, fmaxf(S[nt][2], S[nt][3]));
        }
        mx0 = fmaxf(mx0, __shfl_xor_sync(0xffffffffu, mx0, 1));
        mx0 = fmaxf(mx0, __shfl_xor_sync(0xffffffffu, mx0, 2));
        mx1 = fmaxf(mx1, __shfl_xor_sync(0xffffffffu, mx1, 1));
        mx1 = fmaxf(mx1, __shfl_xor_sync(0xffffffffu, mx1, 2));
        float mn0 = fmaxf(m0, mx0), mn1 = fmaxf(m1, mx1);
        float al0 = __expf(m0 - mn0), al1 = __expf(m1 - mn1);
        float rs0 = 0.0f, rs1 = 0.0f;
        #pragma unroll
        for (int nt = 0; nt < 8; ++nt) {
            if (nt >= nt_max) break;
            float p0 = __expf(S[nt][0] - mn0), p1 = __expf(S[nt][1] - mn0);
            float p2 = __expf(S[nt][2] - mn1), p3 = __expf(S[nt][3] - mn1);
            rs0 += p0 + p1; rs1 += p2 + p3;
            uint2* d0 = (uint2*)(Ps + ((w * 16 + g) * 68 + nt * 8 + 2 * t));
            uint2* d1 = (uint2*)(Ps + ((w * 16 + g + 8) * 68 + nt * 8 + 2 * t));
            *d0 = make_uint2(tf32(p0), tf32(p1));
            *d1 = make_uint2(tf32(p2), tf32(p3));
        }
        rs0 += __shfl_xor_sync(0xffffffffu, rs0, 1);
        rs0 += __shfl_xor_sync(0xffffffffu, rs0, 2);
        rs1 += __shfl_xor_sync(0xffffffffu, rs1, 1);
        rs1 += __shfl_xor_sync(0xffffffffu, rs1, 2);
        l0 = l0 * al0 + rs0; l1 = l1 * al1 + rs1;
        m0 = mn0; m1 = mn1;
        #pragma unroll
        for (int nt = 0; nt < 16; ++nt) {
            O[nt][0] *= al0; O[nt][1] *= al0;
            O[nt][2] *= al1; O[nt][3] *= al1;
        }
        __syncwarp();

        // ---- O += P V ----
        #pragma unroll 8
        for (int ks = 0; ks < 8; ++ks) {
            if (ks >= ks_max) break;
            unsigned af[4];
            af[0] = Ps[(w * 16 + g) * 68 + ks * 8 + t];
            af[1] = Ps[(w * 16 + g + 8) * 68 + ks * 8 + t];
            af[2] = Ps[(w * 16 + g) * 68 + ks * 8 + t + 4];
            af[3] = Ps[(w * 16 + g + 8) * 68 + ks * 8 + t + 4];
            #pragma unroll
            for (int nt = 0; nt < 16; ++nt) {
                unsigned b0 = Vs[(ks * 8 + t) * 136 + nt * 8 + g];
                unsigned b1 = Vs[(ks * 8 + t + 4) * 136 + nt * 8 + g];
                mma8(O[nt], af, b0, b1);
            }
        }
        __syncwarp();
    }

    // ---- normalize and write out[b, row, h*128 + d] ----
    float inv0 = 1.0f / l0, inv1 = 1.0f / l1;
    float* ob0 = out + ((size_t)b * 2048 + (size_t)qt * 64 + w * 16 + g) * 4096 + h * 128;
    float* ob1 = ob0 + (size_t)8 * 4096;
    #pragma unroll
    for (int nt = 0; nt < 16; ++nt) {
        *(float2*)(ob0 + nt * 8 + 2 * t) = make_float2(O[nt][0] * inv0, O[nt][1] * inv0);
        *(float2*)(ob1 + nt * 8 + 2 * t) = make_float2(O[nt][2] * inv1, O[nt][3] * inv1);
    }
}

extern "C" void kernel_launch(void* const* d_in, const int* in_sizes, int n_in,
                              void* d_out, int out_size) {
    int iq = -1;
    for (int i = 0; i < n_in; ++i)
        if (in_sizes[i] == 16777216) { iq = i; break; }
    if (iq < 0) iq = 1;
    const float* q = (const float*)d_in[iq];
    const float* k = (const float*)d_in[iq + 1];
    const float* v = (const float*)d_in[iq + 2];
    float* out = (float*)d_out;

    cudaFuncSetAttribute(fa_tc_kernel,
                         cudaFuncAttributeMaxDynamicSharedMemorySize,
                         SM_WORDS * 4);
    dim3 grid(32, 32, 2);  // q tiles, H, B
    fa_tc_kernel<<<grid, NTH, SM_WORDS * 4>>>(q, k, v, out);
}

// round 5
// speedup vs baseline: 2.9177x; 2.9177x over previous
#include <cuda_runtime.h>
#include <cstddef>

// Causal GQA prefill attention, fp32 I/O. B=2,S=2048,H=32,KVH=8,D=128.
// Flash attention, mma.sync.m16n8k8 tf32. 128 thr = 4 warps, warp owns 16 q-rows.
// All smem XOR-swizzled, unpadded; Q in smem (no register Q cache -> no spills).

#define NTH 128

__device__ __forceinline__ unsigned tf32(float f) {
    unsigned u; asm("cvt.rna.tf32.f32 %0, %1;" : "=r"(u) : "f"(f));
    return u;
}
__device__ __forceinline__ void mma8(float* c, const unsigned* a, unsigned b0, unsigned b1) {
    asm("mma.sync.aligned.m16n8k8.row.col.f32.tf32.tf32.f32 "
        "{%0,%1,%2,%3}, {%4,%5,%6,%7}, {%8,%9}, {%0,%1,%2,%3};"
        : "+f"(c[0]), "+f"(c[1]), "+f"(c[2]), "+f"(c[3])
        : "r"(a[0]), "r"(a[1]), "r"(a[2]), "r"(a[3]), "r"(b0), "r"(b1));
}

// swizzled word index into 64x128 tile (Q,K) / V / 64x64 P
__device__ __forceinline__ int swA(int row, int col) { return row * 128 + (col ^ ((row & 7) << 2)); }
__device__ __forceinline__ int swV(int row, int col) { return row * 128 + (col ^ ((row & 3) << 3)); }
__device__ __forceinline__ int swP(int row, int col) { return row * 64  + (col ^ ((row & 7) << 2)); }

// smem words: Q @0 (8192), K @8192 (8192), V @16384 (8192), P @24576 (4096)
#define SM_Q 0
#define SM_K 8192
#define SM_V 16384
#define SM_P 24576
#define SM_WORDS 28672

__global__ void __launch_bounds__(NTH, 2)
fa_tc2_kernel(const float* __restrict__ q, const float* __restrict__ k,
              const float* __restrict__ v, float* __restrict__ out)
{
    extern __shared__ unsigned sm[];
    unsigned* Qs = sm + SM_Q;
    unsigned* Ks = sm + SM_K;
    unsigned* Vs = sm + SM_V;
    unsigned* Ps = sm + SM_P;

    const int qt   = (int)gridDim.x - 1 - (int)blockIdx.x;  // heavy tiles first
    const int h    = blockIdx.y;
    const int b    = blockIdx.z;
    const int kvh  = h >> 2;
    const int tid  = threadIdx.x;
    const int w    = tid >> 5;
    const int lane = tid & 31;
    const int g    = lane >> 2;   // 0..7
    const int t    = lane & 3;    // 0..3
    const float scale = 0.08838834764831845f;  // 1/sqrt(128)

    // ---- Q tile -> smem tf32 (scale folded), swizzle A, uint4 stores ----
    {
        const float* qb = q + (((size_t)b * 2048 + (size_t)qt * 64) * 32 + h) * 128;
        #pragma unroll
        for (int it = 0; it < 16; ++it) {
            int idx = it * NTH + tid, row = idx >> 5, c = idx & 31;
            float4 a = *(const float4*)(qb + (size_t)row * 4096 + c * 4);
            uint4 u = make_uint4(tf32(a.x * scale), tf32(a.y * scale),
                                 tf32(a.z * scale), tf32(a.w * scale));
            *(uint4*)(Qs + swA(row, c * 4)) = u;
        }
    }

    float O[16][4];
    #pragma unroll
    for (int nt = 0; nt < 16; ++nt)
        #pragma unroll
        for (int r = 0; r < 4; ++r) O[nt][r] = 0.0f;
    float m0 = -1e30f, m1 = -1e30f, l0 = 0.0f, l1 = 0.0f;

    const float* kb0 = k + ((size_t)b * 8 + kvh) * 2048 * 128;
    const float* vb0 = v + ((size_t)b * 8 + kvh) * 2048 * 128;
    const int row0 = qt * 64 + w * 16 + g;
    const int row1 = row0 + 8;

    for (int kt = 0; kt <= qt; ++kt) {
        __syncthreads();
        {
            const float* kb = kb0 + (size_t)kt * 8192;
            const float* vb = vb0 + (size_t)kt * 8192;
            #pragma unroll
            for (int it = 0; it < 16; ++it) {
                int idx = it * NTH + tid, row = idx >> 5, c = idx & 31;
                float4 a = *(const float4*)(kb + idx * 4);
                *(uint4*)(Ks + swA(row, c * 4)) =
                    make_uint4(tf32(a.x), tf32(a.y), tf32(a.z), tf32(a.w));
                float4 e = *(const float4*)(vb + idx * 4);
                *(uint4*)(Vs + swV(row, c * 4)) =
                    make_uint4(tf32(e.x), tf32(e.y), tf32(e.z), tf32(e.w));
            }
        }
        __syncthreads();

        const bool diag = (kt == qt);
        const int nt_max = diag ? 2 * w + 2 : 8;

        // ---- S = (Q*scale) K^T ----
        float S[8][4];
        #pragma unroll
        for (int nt = 0; nt < 8; ++nt)
            #pragma unroll
            for (int r = 0; r < 4; ++r) S[nt][r] = 0.0f;

        #pragma unroll
        for (int ks = 0; ks < 16; ++ks) {
            unsigned af[4];
            af[0] = Qs[swA(w * 16 + g,     ks * 8 + t)];
            af[1] = Qs[swA(w * 16 + g + 8, ks * 8 + t)];
            af[2] = Qs[swA(w * 16 + g,     ks * 8 + t + 4)];
            af[3] = Qs[swA(w * 16 + g + 8, ks * 8 + t + 4)];
            #pragma unroll
            for (int nt = 0; nt < 8; ++nt) {
                if (nt >= nt_max) break;
                unsigned b0 = Ks[swA(nt * 8 + g, ks * 8 + t)];
                unsigned b1 = Ks[swA(nt * 8 + g, ks * 8 + t + 4)];
                mma8(S[nt], af, b0, b1);
            }
        }

        if (diag) {
            #pragma unroll
            for (int nt = 0; nt < 8; ++nt) {
                int c0 = kt * 64 + nt * 8 + 2 * t;
                if (c0 > row0)     S[nt][0] = -1e30f;
                if (c0 + 1 > row0) S[nt][1] = -1e30f;
                if (c0 > row1)     S[nt][2] = -1e30f;
                if (c0 + 1 > row1) S[nt][3] = -1e30f;
            }
        }

        // ---- online softmax ----
        float mx0 = -1e30f, mx1 = -1e30f;
        #pragma unroll
        for (int nt = 0; nt < 8; ++nt) {
            if (nt >= nt_max) break;
            mx0 = fmaxf(mx0, fmaxf(S[nt][0], S[nt][1]));
            mx1 = fmaxf(mx1, fmaxf(S[nt][2], S[nt][3]));
        }
        mx0 = fmaxf(mx0, __shfl_xor_sync(0xffffffffu, mx0, 1));
        mx0 = fmaxf(mx0, __shfl_xor_sync(0xffffffffu, mx0, 2));
        mx1 = fmaxf(mx1, __shfl_xor_sync(0xffffffffu, mx1, 1));
        mx1 = fmaxf(mx1, __shfl_xor_sync(0xffffffffu, mx1, 2));
        float mn0 = fmaxf(m0, mx0), mn1 = fmaxf(m1, mx1);
        float al0 = __expf(m0 - mn0), al1 = __expf(m1 - mn1);
        float rs0 = 0.0f, rs1 = 0.0f;
        #pragma unroll
        for (int nt = 0; nt < 8; ++nt) {
            if (nt >= nt_max) break;
            float p0 = __expf(S[nt][0] - mn0), p1 = __expf(S[nt][1] - mn0);
            float p2 = __expf(S[nt][2] - mn1), p3 = __expf(S[nt][3] - mn1);
            rs0 += p0 + p1; rs1 += p2 + p3;
            *(uint2*)(Ps + swP(w * 16 + g,     nt * 8 + 2 * t)) = make_uint2(tf32(p0), tf32(p1));
            *(uint2*)(Ps + swP(w * 16 + g + 8, nt * 8 + 2 * t)) = make_uint2(tf32(p2), tf32(p3));
        }
        rs0 += __shfl_xor_sync(0xffffffffu, rs0, 1);
        rs0 += __shfl_xor_sync(0xffffffffu, rs0, 2);
        rs1 += __shfl_xor_sync(0xffffffffu, rs1, 1);
        rs1 += __shfl_xor_sync(0xffffffffu, rs1, 2);
        l0 = l0 * al0 + rs0; l1 = l1 * al1 + rs1;
        m0 = mn0; m1 = mn1;
        #pragma unroll
        for (int nt = 0; nt < 16; ++nt) {
            O[nt][0] *= al0; O[nt][1] *= al0;
            O[nt][2] *= al1; O[nt][3] *= al1;
        }
        __syncwarp();

        // ---- O += P V ----
        #pragma unroll
        for (int ks = 0; ks < 8; ++ks) {
            if (ks >= nt_max) break;   // stale P beyond nt_max must be skipped
            unsigned af[4];
            af[0] = Ps[swP(w * 16 + g,     ks * 8 + t)];
            af[1] = Ps[swP(w * 16 + g + 8, ks * 8 + t)];
            af[2] = Ps[swP(w * 16 + g,     ks * 8 + t + 4)];
            af[3] = Ps[swP(w * 16 + g + 8, ks * 8 + t + 4)];
            #pragma unroll
            for (int nt = 0; nt < 16; ++nt) {
                unsigned b0 = Vs[swV(ks * 8 + t,     nt * 8 + g)];
                unsigned b1 = Vs[swV(ks * 8 + t + 4, nt * 8 + g)];
                mma8(O[nt], af, b0, b1);
            }
        }
        __syncwarp();
    }

    // ---- normalize + write out[b, row, h*128 + d] ----
    float inv0 = 1.0f / l0, inv1 = 1.0f / l1;
    float* ob0 = out + ((size_t)b * 2048 + (size_t)qt * 64 + w * 16 + g) * 4096 + h * 128;
    float* ob1 = ob0 + (size_t)8 * 4096;
    #pragma unroll
    for (int nt = 0; nt < 16; ++nt) {
        *(float2*)(ob0 + nt * 8 + 2 * t) = make_float2(O[nt][0] * inv0, O[nt][1] * inv0);
        *(float2*)(ob1 + nt * 8 + 2 * t) = make_float2(O[nt][2] * inv1, O[nt][3] * inv1);
    }
}

extern "C" void kernel_launch(void* const* d_in, const int* in_sizes, int n_in,
                              void* d_out, int out_size) {
    int iq = -1;
    for (int i = 0; i < n_in; ++i)
        if (in_sizes[i] == 16777216) { iq = i; break; }
    if (iq < 0) iq = 1;
    const float* q = (const float*)d_in[iq];
    const float* k = (const float*)d_in[iq + 1];
    const float* v = (const float*)d_in[iq + 2];
    float* out = (float*)d_out;

    cudaFuncSetAttribute(fa_tc2_kernel,
                         cudaFuncAttributeMaxDynamicSharedMemorySize,
                         SM_WORDS * 4);
    dim3 grid(32, 32, 2);  // q tiles, H, B
    fa_tc2_kernel<<<grid, NTH, SM_WORDS * 4>>>(q, k, v, out);
}